// round 1
// baseline (speedup 1.0000x reference)
#include <cuda_runtime.h>

#define POLAR_SCALE 0.125f
#define QJL_SCALE   0.01f
#define BM   32      // Q rows per CTA
#define BN   64      // KV rows per tile
#define HD   64      // head dim
#define SEQ  2048
#define NT   128     // threads per CTA

// Layouts (all float, word-granularity XOR swizzle on bits [2:..] of the column):
//   Qs[d][m]  : HD x BM, vec4-col swizzled by (d>>2)&7   (8 KB)
//   Ks[d][n]  : HD x BN, vec4-col swizzled by (d>>2)&15  (16 KB)
//   Vs[n][dv] : BN x HD, natural row-major               (16 KB)
//   Ps[n][m]  : BN x BM (P transposed), swizzled by (n>>2)&7 (8 KB)
// Total static smem = 49152 B exactly.

__global__ void __launch_bounds__(NT, 4) tq_attn_kernel(
    const float* __restrict__ q,
    const float* __restrict__ kp,
    const float* __restrict__ kq,
    const float* __restrict__ vp,
    const float* __restrict__ vq,
    float* __restrict__ out)
{
    __shared__ float Qs[HD * BM];
    __shared__ float Ks[HD * BN];
    __shared__ float Vs[BN * HD];
    __shared__ float Ps[BN * BM];

    const int tid = threadIdx.x;
    const int tx  = tid & 15;   // -> n4 (QK) / dv4 (PV)
    const int ty  = tid >> 4;   // -> m4
    const int m0  = blockIdx.x * BM;
    const size_t base = (size_t)blockIdx.y * (size_t)(SEQ * HD);

    const float* qb  = q  + base + (size_t)m0 * HD;
    const float* kpb = kp + base;
    const float* kqb = kq + base;
    const float* vpb = vp + base;
    const float* vqb = vq + base;

    const float qsc = 0.125f * 1.4426950408889634f;  // 1/sqrt(64) * log2(e)

    // ---- Load Q (BM x HD), store transposed + swizzled: Qs[d][m] ----
    #pragma unroll
    for (int it = 0; it < (BM * HD / 4) / NT; ++it) {   // 4 iters
        int idx = tid + it * NT;          // 0..511
        int m = idx >> 4;                 // 0..31
        int k = idx & 15;                 // d-vec 0..15
        float4 v = *reinterpret_cast<const float4*>(qb + m * HD + k * 4);
        int cw = m ^ (4 * (k & 7));       // swizzled word-col in [0,32)
        Qs[(4 * k + 0) * BM + cw] = v.x * qsc;
        Qs[(4 * k + 1) * BM + cw] = v.y * qsc;
        Qs[(4 * k + 2) * BM + cw] = v.z * qsc;
        Qs[(4 * k + 3) * BM + cw] = v.w * qsc;
    }

    float o[4][4];
    #pragma unroll
    for (int i = 0; i < 4; ++i)
        #pragma unroll
        for (int j = 0; j < 4; ++j) o[i][j] = 0.f;
    float rmax[4] = {-1e30f, -1e30f, -1e30f, -1e30f};
    float rsum[4] = {0.f, 0.f, 0.f, 0.f};

    for (int n0 = 0; n0 < SEQ; n0 += BN) {
        __syncthreads();   // protect Ks/Vs (and Ps) from previous iteration readers

        // ---- Load + dequant K tile (transposed+swizzled) and V tile (natural) ----
        #pragma unroll
        for (int it = 0; it < (BN * HD / 4) / NT; ++it) {  // 8 iters
            int idx = tid + it * NT;       // 0..1023
            int n = idx >> 4;              // 0..63
            int k = idx & 15;
            size_t goff = (size_t)(n0 + n) * HD + k * 4;
            float4 ap = *reinterpret_cast<const float4*>(kpb + goff);
            float4 aq = *reinterpret_cast<const float4*>(kqb + goff);
            int cw = n ^ (4 * (k & 15));   // swizzled word-col in [0,64)
            Ks[(4 * k + 0) * BN + cw] = ap.x * POLAR_SCALE + aq.x * QJL_SCALE;
            Ks[(4 * k + 1) * BN + cw] = ap.y * POLAR_SCALE + aq.y * QJL_SCALE;
            Ks[(4 * k + 2) * BN + cw] = ap.z * POLAR_SCALE + aq.z * QJL_SCALE;
            Ks[(4 * k + 3) * BN + cw] = ap.w * POLAR_SCALE + aq.w * QJL_SCALE;

            float4 bp = *reinterpret_cast<const float4*>(vpb + goff);
            float4 bq = *reinterpret_cast<const float4*>(vqb + goff);
            float4 vv;
            vv.x = bp.x * POLAR_SCALE + bq.x * QJL_SCALE;
            vv.y = bp.y * POLAR_SCALE + bq.y * QJL_SCALE;
            vv.z = bp.z * POLAR_SCALE + bq.z * QJL_SCALE;
            vv.w = bp.w * POLAR_SCALE + bq.w * QJL_SCALE;
            *reinterpret_cast<float4*>(&Vs[n * HD + k * 4]) = vv;
        }
        __syncthreads();

        // ---- S = (Q*qsc) K^T : per-d rank-1 outer products ----
        float s[4][4];
        #pragma unroll
        for (int i = 0; i < 4; ++i)
            #pragma unroll
            for (int j = 0; j < 4; ++j) s[i][j] = 0.f;

        #pragma unroll 8
        for (int d = 0; d < HD; ++d) {
            float4 av = *reinterpret_cast<const float4*>(
                &Qs[d * BM + ((ty ^ ((d >> 2) & 7)) << 2)]);
            float4 bv = *reinterpret_cast<const float4*>(
                &Ks[d * BN + ((tx ^ ((d >> 2) & 15)) << 2)]);
            s[0][0] = fmaf(av.x, bv.x, s[0][0]);
            s[0][1] = fmaf(av.x, bv.y, s[0][1]);
            s[0][2] = fmaf(av.x, bv.z, s[0][2]);
            s[0][3] = fmaf(av.x, bv.w, s[0][3]);
            s[1][0] = fmaf(av.y, bv.x, s[1][0]);
            s[1][1] = fmaf(av.y, bv.y, s[1][1]);
            s[1][2] = fmaf(av.y, bv.z, s[1][2]);
            s[1][3] = fmaf(av.y, bv.w, s[1][3]);
            s[2][0] = fmaf(av.z, bv.x, s[2][0]);
            s[2][1] = fmaf(av.z, bv.y, s[2][1]);
            s[2][2] = fmaf(av.z, bv.z, s[2][2]);
            s[2][3] = fmaf(av.z, bv.w, s[2][3]);
            s[3][0] = fmaf(av.w, bv.x, s[3][0]);
            s[3][1] = fmaf(av.w, bv.y, s[3][1]);
            s[3][2] = fmaf(av.w, bv.z, s[3][2]);
            s[3][3] = fmaf(av.w, bv.w, s[3][3]);
        }

        // ---- Online softmax (scores already in log2 domain) ----
        #pragma unroll
        for (int i = 0; i < 4; ++i) {
            float mx = fmaxf(fmaxf(s[i][0], s[i][1]), fmaxf(s[i][2], s[i][3]));
            #pragma unroll
            for (int off = 1; off < 16; off <<= 1)
                mx = fmaxf(mx, __shfl_xor_sync(0xffffffffu, mx, off));
            float nm = fmaxf(rmax[i], mx);
            float alpha = exp2f(rmax[i] - nm);
            rmax[i] = nm;
            float ps = 0.f;
            #pragma unroll
            for (int j = 0; j < 4; ++j) {
                s[i][j] = exp2f(s[i][j] - nm);
                ps += s[i][j];
            }
            rsum[i] = rsum[i] * alpha + ps;   // per-thread partial over tx
            #pragma unroll
            for (int j = 0; j < 4; ++j) o[i][j] *= alpha;
        }

        // ---- Store P transposed + swizzled: Ps[n][m] ----
        #pragma unroll
        for (int j = 0; j < 4; ++j) {
            int n = tx * 4 + j;
            int rowbase = n * BM;
            int sw = 4 * (tx & 7);    // (n>>2)&7 == tx&7
            #pragma unroll
            for (int i = 0; i < 4; ++i)
                Ps[rowbase + ((ty * 4 + i) ^ sw)] = s[i][j];
        }
        __syncthreads();

        // ---- O += P V : per-n rank-1 outer products ----
        #pragma unroll 8
        for (int n = 0; n < BN; ++n) {
            float4 av = *reinterpret_cast<const float4*>(
                &Ps[n * BM + ((ty ^ ((n >> 2) & 7)) << 2)]);
            float4 bv = *reinterpret_cast<const float4*>(
                &Vs[n * HD + (tx << 2)]);
            o[0][0] = fmaf(av.x, bv.x, o[0][0]);
            o[0][1] = fmaf(av.x, bv.y, o[0][1]);
            o[0][2] = fmaf(av.x, bv.z, o[0][2]);
            o[0][3] = fmaf(av.x, bv.w, o[0][3]);
            o[1][0] = fmaf(av.y, bv.x, o[1][0]);
            o[1][1] = fmaf(av.y, bv.y, o[1][1]);
            o[1][2] = fmaf(av.y, bv.z, o[1][2]);
            o[1][3] = fmaf(av.y, bv.w, o[1][3]);
            o[2][0] = fmaf(av.z, bv.x, o[2][0]);
            o[2][1] = fmaf(av.z, bv.y, o[2][1]);
            o[2][2] = fmaf(av.z, bv.z, o[2][2]);
            o[2][3] = fmaf(av.z, bv.w, o[2][3]);
            o[3][0] = fmaf(av.w, bv.x, o[3][0]);
            o[3][1] = fmaf(av.w, bv.y, o[3][1]);
            o[3][2] = fmaf(av.w, bv.z, o[3][2]);
            o[3][3] = fmaf(av.w, bv.w, o[3][3]);
        }
    }

    // ---- Epilogue: reduce row sums over tx, normalize, store ----
    #pragma unroll
    for (int i = 0; i < 4; ++i) {
        float sm = rsum[i];
        #pragma unroll
        for (int off = 1; off < 16; off <<= 1)
            sm += __shfl_xor_sync(0xffffffffu, sm, off);
        float inv = 1.0f / sm;
        float4 r;
        r.x = o[i][0] * inv;
        r.y = o[i][1] * inv;
        r.z = o[i][2] * inv;
        r.w = o[i][3] * inv;
        *reinterpret_cast<float4*>(
            out + base + (size_t)(m0 + ty * 4 + i) * HD + (tx << 2)) = r;
    }
}

extern "C" void kernel_launch(void* const* d_in, const int* in_sizes, int n_in,
                              void* d_out, int out_size)
{
    const float* q  = (const float*)d_in[0];
    const float* kp = (const float*)d_in[1];
    const float* kq = (const float*)d_in[2];
    const float* vp = (const float*)d_in[3];
    const float* vq = (const float*)d_in[4];
    float* out = (float*)d_out;

    int bh = in_sizes[0] / (SEQ * HD);   // B*H = 32
    dim3 grid(SEQ / BM, bh);
    tq_attn_kernel<<<grid, NT>>>(q, kp, kq, vp, vq, out);
}